// round 1
// baseline (speedup 1.0000x reference)
#include <cuda_runtime.h>
#include <math.h>

#define Bz 8
#define Sq 1024
#define Cc 1280
#define Hh 8
#define DHd 160
#define RK 4
#define Mrows (Bz*Sq)      /* 8192 */
#define QKV_N (3*Cc)       /* 3840 */

// ---------------- scratch (device globals; no allocation) ----------------
__device__ float g_hp[(size_t)Mrows*Cc];              // h + pose
__device__ float g_x[(size_t)Mrows*Cc];               // merged x
__device__ float g_qkv[(size_t)Mrows*QKV_N];          // q|k|v concat
__device__ float g_weff[(size_t)Cc*QKV_N];            // Wq|Wk|Wv with LoRA folded
__device__ float g_woeff[(size_t)Cc*Cc];              // Wo with LoRA folded
__device__ float g_probs[(size_t)Bz*Hh*Sq*Sq];        // attention probs (256MB)
__device__ float g_attn[(size_t)Mrows*Cc];            // attention output

// ---------------- elementwise add ----------------
__global__ void k_add(const float* __restrict__ a, const float* __restrict__ b,
                      float* __restrict__ c, int n) {
    int i = blockIdx.x * 256 + threadIdx.x;
    if (i < n) c[i] = a[i] + b[i];
}

// ---------------- fold LoRA into weight: dst[k, dstoff+n] = W[k,n] + sum_r dn[k,r]*up[r,n]
__global__ void k_weff(const float* __restrict__ W, const float* __restrict__ dn,
                       const float* __restrict__ up, float* __restrict__ dst,
                       int dstld, int dstoff) {
    int i = blockIdx.x * 256 + threadIdx.x;
    if (i >= Cc * Cc) return;
    int k = i / Cc, n = i % Cc;
    float s = W[i];
#pragma unroll
    for (int r = 0; r < RK; r++) s += dn[k * RK + r] * up[r * Cc + n];
    dst[(size_t)k * dstld + dstoff + n] = s;
}

// ---------------- big SGEMM: C[M,N] = A[M,K] @ B[K,N] (+epilogue) ----------------
// 128x128 block tile, 256 threads, 8x8 microtile, K-chunk 8.
// EPI: 0 = none, 1 = + bias[n] + resid[m*N+n], 2 = + bias[n]
template <int EPI>
__global__ void k_gemm128(const float* __restrict__ A, const float* __restrict__ Bm,
                          float* __restrict__ Cm, int M, int N, int K,
                          const float* __restrict__ bias, const float* __restrict__ resid) {
    __shared__ float As[8][128];
    __shared__ float Bs[8][128];
    const int tid = threadIdx.x;
    const int m0 = blockIdx.y * 128, n0 = blockIdx.x * 128;
    const int arow = tid >> 1, acol = (tid & 1) * 4;
    const int brow = tid >> 5, bcol = (tid & 31) * 4;
    const int tx = tid & 15, ty = tid >> 4;

    float acc[8][8] = {};
    const float* Ap = A + (size_t)(m0 + arow) * K + acol;
    const float* Bp = Bm + (size_t)brow * N + n0 + bcol;

    for (int kk = 0; kk < K; kk += 8) {
        float4 av = *(const float4*)(Ap + kk);
        As[acol + 0][arow] = av.x;
        As[acol + 1][arow] = av.y;
        As[acol + 2][arow] = av.z;
        As[acol + 3][arow] = av.w;
        float4 bv = *(const float4*)(Bp + (size_t)kk * N);
        *(float4*)&Bs[brow][bcol] = bv;
        __syncthreads();
#pragma unroll
        for (int k = 0; k < 8; k++) {
            float a[8], b[8];
            *(float4*)(a) = *(const float4*)&As[k][ty * 8];
            *(float4*)(a + 4) = *(const float4*)&As[k][ty * 8 + 4];
            *(float4*)(b) = *(const float4*)&Bs[k][tx * 8];
            *(float4*)(b + 4) = *(const float4*)&Bs[k][tx * 8 + 4];
#pragma unroll
            for (int i = 0; i < 8; i++)
#pragma unroll
                for (int j = 0; j < 8; j++) acc[i][j] = fmaf(a[i], b[j], acc[i][j]);
        }
        __syncthreads();
    }

#pragma unroll
    for (int i = 0; i < 8; i++) {
        int row = m0 + ty * 8 + i;
        float* cp = Cm + (size_t)row * N + n0 + tx * 8;
#pragma unroll
        for (int j = 0; j < 8; j += 4) {
            float4 v;
            v.x = acc[i][j + 0]; v.y = acc[i][j + 1]; v.z = acc[i][j + 2]; v.w = acc[i][j + 3];
            int col = n0 + tx * 8 + j;
            if (EPI >= 1) {
                float4 bb = *(const float4*)(bias + col);
                v.x += bb.x; v.y += bb.y; v.z += bb.z; v.w += bb.w;
            }
            if (EPI == 1) {
                float4 rr = *(const float4*)(resid + (size_t)row * N + col);
                v.x += rr.x; v.y += rr.y; v.z += rr.z; v.w += rr.w;
            }
            *(float4*)(cp + j) = v;
        }
    }
}

// ---------------- scores = scale * Q @ K^T per (b,h) ----------------
// 128x128 tile over [Sq, Sq], K-dim = DHd = 160
__global__ void k_score(const float* __restrict__ qkv, float* __restrict__ probs) {
    __shared__ float As[8][128];
    __shared__ float Bs[8][128];
    const int tid = threadIdx.x;
    const int bh = blockIdx.z;
    const int b = bh >> 3, h = bh & 7;
    const float* Aq = qkv + (size_t)b * Sq * QKV_N + h * DHd;
    const float* Bk = Aq + Cc;
    float* Cp = probs + (size_t)bh * Sq * Sq;
    const int m0 = blockIdx.y * 128, n0 = blockIdx.x * 128;
    const int arow = tid >> 1, acol = (tid & 1) * 4;
    const int tx = tid & 15, ty = tid >> 4;

    float acc[8][8] = {};
    const float* Ap = Aq + (size_t)(m0 + arow) * QKV_N + acol;
    const float* Bp = Bk + (size_t)(n0 + arow) * QKV_N + acol;

    for (int kk = 0; kk < DHd; kk += 8) {
        float4 av = *(const float4*)(Ap + kk);
        As[acol + 0][arow] = av.x;
        As[acol + 1][arow] = av.y;
        As[acol + 2][arow] = av.z;
        As[acol + 3][arow] = av.w;
        float4 bv = *(const float4*)(Bp + kk);
        Bs[acol + 0][arow] = bv.x;
        Bs[acol + 1][arow] = bv.y;
        Bs[acol + 2][arow] = bv.z;
        Bs[acol + 3][arow] = bv.w;
        __syncthreads();
#pragma unroll
        for (int k = 0; k < 8; k++) {
            float a[8], b2[8];
            *(float4*)(a) = *(const float4*)&As[k][ty * 8];
            *(float4*)(a + 4) = *(const float4*)&As[k][ty * 8 + 4];
            *(float4*)(b2) = *(const float4*)&Bs[k][tx * 8];
            *(float4*)(b2 + 4) = *(const float4*)&Bs[k][tx * 8 + 4];
#pragma unroll
            for (int i = 0; i < 8; i++)
#pragma unroll
                for (int j = 0; j < 8; j++) acc[i][j] = fmaf(a[i], b2[j], acc[i][j]);
        }
        __syncthreads();
    }

    const float scale = 0.07905694150420949f;  // 160^-0.5
#pragma unroll
    for (int i = 0; i < 8; i++) {
        float* cp = Cp + (size_t)(m0 + ty * 8 + i) * Sq + n0 + tx * 8;
#pragma unroll
        for (int j = 0; j < 8; j += 4) {
            float4 v;
            v.x = acc[i][j + 0] * scale; v.y = acc[i][j + 1] * scale;
            v.z = acc[i][j + 2] * scale; v.w = acc[i][j + 3] * scale;
            *(float4*)(cp + j) = v;
        }
    }
}

// ---------------- row softmax over Sq=1024, one block per row ----------------
__global__ void k_softmax(float* __restrict__ probs) {
    __shared__ float red[8];
    const size_t row = blockIdx.x;
    float* p = probs + row * (size_t)Sq;
    const int t = threadIdx.x;
    float4 v = *(float4*)(p + t * 4);

    float m = fmaxf(fmaxf(v.x, v.y), fmaxf(v.z, v.w));
#pragma unroll
    for (int o = 16; o; o >>= 1) m = fmaxf(m, __shfl_xor_sync(0xffffffffu, m, o));
    if ((t & 31) == 0) red[t >> 5] = m;
    __syncthreads();
    m = red[0];
#pragma unroll
    for (int i = 1; i < 8; i++) m = fmaxf(m, red[i]);
    __syncthreads();

    v.x = expf(v.x - m); v.y = expf(v.y - m); v.z = expf(v.z - m); v.w = expf(v.w - m);
    float s = v.x + v.y + v.z + v.w;
#pragma unroll
    for (int o = 16; o; o >>= 1) s += __shfl_xor_sync(0xffffffffu, s, o);
    if ((t & 31) == 0) red[t >> 5] = s;
    __syncthreads();
    s = 0.f;
#pragma unroll
    for (int i = 0; i < 8; i++) s += red[i];
    float inv = 1.0f / s;
    v.x *= inv; v.y *= inv; v.z *= inv; v.w *= inv;
    *(float4*)(p + t * 4) = v;
}

// ---------------- out = probs @ V per (b,h); 64x64 tile, K-chunk 16 ----------------
__global__ void k_av(const float* __restrict__ probs, const float* __restrict__ qkv,
                     float* __restrict__ attn) {
    __shared__ float As[16][64];
    __shared__ float Bs[16][64];
    const int tid = threadIdx.x;
    const int bh = blockIdx.z;
    const int b = bh >> 3, h = bh & 7;
    const float* P = probs + (size_t)bh * Sq * Sq;
    const float* V = qkv + (size_t)b * Sq * QKV_N + 2 * Cc + h * DHd;
    const int m0 = blockIdx.y * 64, n0 = blockIdx.x * 64;
    const int arow = tid >> 2, acol = (tid & 3) * 4;
    const int brow = tid >> 4, bcol = (tid & 15) * 4;
    const bool bvalid = (n0 + bcol) < DHd;
    const int tx = tid & 15, ty = tid >> 4;

    float acc[4][4] = {};
    for (int kk = 0; kk < Sq; kk += 16) {
        float4 av = *(const float4*)(P + (size_t)(m0 + arow) * Sq + kk + acol);
        As[acol + 0][arow] = av.x;
        As[acol + 1][arow] = av.y;
        As[acol + 2][arow] = av.z;
        As[acol + 3][arow] = av.w;
        float4 bv = make_float4(0.f, 0.f, 0.f, 0.f);
        if (bvalid) bv = *(const float4*)(V + (size_t)(kk + brow) * QKV_N + n0 + bcol);
        *(float4*)&Bs[brow][bcol] = bv;
        __syncthreads();
#pragma unroll
        for (int k = 0; k < 16; k++) {
            float a[4], b2[4];
            *(float4*)(a) = *(const float4*)&As[k][ty * 4];
            *(float4*)(b2) = *(const float4*)&Bs[k][tx * 4];
#pragma unroll
            for (int i = 0; i < 4; i++)
#pragma unroll
                for (int j = 0; j < 4; j++) acc[i][j] = fmaf(a[i], b2[j], acc[i][j]);
        }
        __syncthreads();
    }

    const int dbase = n0 + tx * 4;
    if (dbase < DHd) {
#pragma unroll
        for (int i = 0; i < 4; i++) {
            float* op = attn + (size_t)(b * Sq + m0 + ty * 4 + i) * Cc + h * DHd + dbase;
            float4 st;
            st.x = acc[i][0]; st.y = acc[i][1]; st.z = acc[i][2]; st.w = acc[i][3];
            *(float4*)op = st;
        }
    }
}

// ---------------- launch ----------------
extern "C" void kernel_launch(void* const* d_in, const int* in_sizes, int n_in,
                              void* d_out, int out_size) {
    const float* h  = (const float*)d_in[0];
    const float* p  = (const float*)d_in[1];
    const float* Wm = (const float*)d_in[2];
    const float* bm = (const float*)d_in[3];
    const float* wq = (const float*)d_in[4];
    const float* wk = (const float*)d_in[5];
    const float* wv = (const float*)d_in[6];
    const float* wo = (const float*)d_in[7];
    const float* bo = (const float*)d_in[8];
    const float* qd = (const float*)d_in[9];
    const float* qu = (const float*)d_in[10];
    const float* kd = (const float*)d_in[11];
    const float* ku = (const float*)d_in[12];
    const float* vd = (const float*)d_in[13];
    const float* vu = (const float*)d_in[14];
    const float* od = (const float*)d_in[15];
    const float* ou = (const float*)d_in[16];

    float *hp, *x, *qkv, *weff, *woeff, *probs, *attn;
    cudaGetSymbolAddress((void**)&hp, g_hp);
    cudaGetSymbolAddress((void**)&x, g_x);
    cudaGetSymbolAddress((void**)&qkv, g_qkv);
    cudaGetSymbolAddress((void**)&weff, g_weff);
    cudaGetSymbolAddress((void**)&woeff, g_woeff);
    cudaGetSymbolAddress((void**)&probs, g_probs);
    cudaGetSymbolAddress((void**)&attn, g_attn);

    // 1) hp = h + pose
    int n1 = Mrows * Cc;
    k_add<<<(n1 + 255) / 256, 256>>>(h, p, hp, n1);

    // 2) fold LoRA into weights
    int gw = (Cc * Cc + 255) / 256;
    k_weff<<<gw, 256>>>(wq, qd, qu, weff, QKV_N, 0);
    k_weff<<<gw, 256>>>(wk, kd, ku, weff, QKV_N, Cc);
    k_weff<<<gw, 256>>>(wv, vd, vu, weff, QKV_N, 2 * Cc);
    k_weff<<<gw, 256>>>(wo, od, ou, woeff, Cc, 0);

    // 3) x = hp @ Wm + bm + h
    k_gemm128<1><<<dim3(Cc / 128, Mrows / 128), 256>>>(hp, Wm, x, Mrows, Cc, Cc, bm, h);

    // 4) qkv = x @ weff  (N = 3840)
    k_gemm128<0><<<dim3(QKV_N / 128, Mrows / 128), 256>>>(x, weff, qkv, Mrows, QKV_N, Cc,
                                                          nullptr, nullptr);

    // 5) scores + softmax + PV
    k_score<<<dim3(Sq / 128, Sq / 128, Bz * Hh), 256>>>(qkv, probs);
    k_softmax<<<Bz * Hh * Sq, 256>>>(probs);
    k_av<<<dim3(3, Sq / 64, Bz * Hh), 256>>>(probs, qkv, attn);

    // 6) out = attn @ woeff + bo
    k_gemm128<2><<<dim3(Cc / 128, Mrows / 128), 256>>>(attn, woeff, (float*)d_out,
                                                       Mrows, Cc, Cc, bo, nullptr);
}

// round 3
// speedup vs baseline: 1.6983x; 1.6983x over previous
#include <cuda_runtime.h>
#include <cuda_bf16.h>
#include <cstdint>
#include <math.h>

#define Bz 8
#define Sq 1024
#define Cc 1280
#define Hh 8
#define DHd 160
#define RK 4
#define Mrows (Bz*Sq)      /* 8192 */
#define QKV_N (3*Cc)       /* 3840 */
#define KP (3*Cc)          /* K' = 3840 (hi|lo|hi split concat) */
#define KI (KP/64)         /* 60 k-chunks of 64 */

// ====================== small helpers ======================
__device__ __forceinline__ uint32_t smem_u32(const void* p) {
    uint32_t a;
    asm("{ .reg .u64 t; cvta.to.shared.u64 t, %1; cvt.u32.u64 %0, t; }" : "=r"(a) : "l"(p));
    return a;
}
__device__ __forceinline__ void cpa16(uint32_t dst, const void* src) {
    asm volatile("cp.async.cg.shared.global [%0], [%1], 16;" :: "r"(dst), "l"(src) : "memory");
}
#define CP_COMMIT asm volatile("cp.async.commit_group;" ::: "memory")
#define CP_WAIT2  asm volatile("cp.async.wait_group 2;" ::: "memory")

__device__ __forceinline__ void ldsm4(uint32_t* r, uint32_t addr) {
    asm volatile("ldmatrix.sync.aligned.m8n8.x4.shared.b16 {%0,%1,%2,%3}, [%4];"
                 : "=r"(r[0]), "=r"(r[1]), "=r"(r[2]), "=r"(r[3]) : "r"(addr));
}
__device__ __forceinline__ void mma16816(float* d, const uint32_t* a, const uint32_t* b) {
    asm volatile(
        "mma.sync.aligned.m16n8k16.row.col.f32.bf16.bf16.f32 "
        "{%0,%1,%2,%3}, {%4,%5,%6,%7}, {%8,%9}, {%0,%1,%2,%3};"
        : "+f"(d[0]), "+f"(d[1]), "+f"(d[2]), "+f"(d[3])
        : "r"(a[0]), "r"(a[1]), "r"(a[2]), "r"(a[3]), "r"(b[0]), "r"(b[1]));
}
__device__ __forceinline__ void split_bf(float v, __nv_bfloat16& h, __nv_bfloat16& l) {
    h = __float2bfloat16(v);
    l = __float2bfloat16(v - __bfloat162float(h));
}
// write split activation pair: A' layout = [hi | lo | hi] along K'
__device__ __forceinline__ void wr_splitA(__nv_bfloat16* Cs, size_t base, float v0, float v1) {
    __nv_bfloat16 h0, l0, h1, l1;
    split_bf(v0, h0, l0);
    split_bf(v1, h1, l1);
    __nv_bfloat162 hh, ll;
    hh.x = h0; hh.y = h1; ll.x = l0; ll.y = l1;
    uint32_t uh = *(uint32_t*)&hh, ul = *(uint32_t*)&ll;
    *(uint32_t*)((char*)(Cs + base))          = uh;
    *(uint32_t*)((char*)(Cs + base + Cc))     = ul;
    *(uint32_t*)((char*)(Cs + base + 2 * Cc)) = uh;
}

// ====================== scratch ======================
__device__ __nv_bfloat16 g_hp2[(size_t)Mrows * KP];   // [hi|lo|hi] of h+pose
__device__ __nv_bfloat16 g_x2[(size_t)Mrows * KP];    // [hi|lo|hi] of x
__device__ __nv_bfloat16 g_at2[(size_t)Mrows * KP];   // [hi|lo|hi] of attn out
__device__ __nv_bfloat16 g_wm2[(size_t)Cc * KP];      // B' of Wm     [N][K']
__device__ __nv_bfloat16 g_we2[(size_t)QKV_N * KP];   // B' of Wq|k|v [N][K']
__device__ __nv_bfloat16 g_wo2[(size_t)Cc * KP];      // B' of Wo     [N][K']
__device__ float g_qkv[(size_t)Mrows * QKV_N];
__device__ float g_probs[(size_t)Bz * Hh * Sq * Sq];

// ====================== prep kernels ======================
__global__ void k_add_split(const float* __restrict__ a, const float* __restrict__ b,
                            __nv_bfloat16* __restrict__ dst, int n) {
    int i = blockIdx.x * 256 + threadIdx.x;
    if (i >= n) return;
    float v = a[i] + b[i];
    int row = i / Cc, k = i - row * Cc;
    size_t base = (size_t)row * KP + k;
    __nv_bfloat16 hi, lo;
    split_bf(v, hi, lo);
    dst[base] = hi;
    dst[base + Cc] = lo;
    dst[base + 2 * Cc] = hi;
}

// B' builder: W[k][n] (+LoRA) -> dst[(off+n)*KP + {k: hi, k+Cc: hi, k+2Cc: lo}]
__global__ void k_wT_split(const float* __restrict__ W, const float* __restrict__ dn,
                           const float* __restrict__ up, __nv_bfloat16* __restrict__ dst,
                           int dstoff) {
    int i = blockIdx.x * 256 + threadIdx.x;
    if (i >= Cc * Cc) return;
    int k = i / Cc, n = i - k * Cc;
    float s = W[i];
    if (dn != nullptr) {
#pragma unroll
        for (int r = 0; r < RK; r++) s += dn[k * RK + r] * up[r * Cc + n];
    }
    size_t base = (size_t)(dstoff + n) * KP + k;
    __nv_bfloat16 hi, lo;
    split_bf(s, hi, lo);
    dst[base] = hi;
    dst[base + Cc] = hi;
    dst[base + 2 * Cc] = lo;
}

// ====================== HMMA GEMM: C[M,N] = A'[M,K'] @ B'[N,K']^T ======================
// 128x128 CTA tile, 8 warps (2M x 4N -> 64x32 warp tile), 3-stage cp.async pipeline.
// MODE 0: fp32 out.  MODE 1: +bias +resid, split-write A' bf16.  MODE 2: +bias, fp32 out.
template <int MODE>
__global__ void __launch_bounds__(256, 1) k_mma(
    const __nv_bfloat16* __restrict__ A, const __nv_bfloat16* __restrict__ B, int N,
    float* __restrict__ Cf, __nv_bfloat16* __restrict__ Cs,
    const float* __restrict__ bias, const float* __restrict__ resid) {
    extern __shared__ char sm[];
    const uint32_t sb = smem_u32(sm);
    const int tid = threadIdx.x, lane = tid & 31, wid = tid >> 5;
    const int m0 = blockIdx.y * 128, n0 = blockIdx.x * 128;
    const int wm = (wid >> 2) * 64, wn = (wid & 3) * 32;

    float acc[4][4][4] = {};

    // ---- pipeline loads: stage s holds A tile (16KB) + B tile (16KB) ----
#define LOAD_STAGE(s, c) do { \
        uint32_t Ad = sb + (s) * 32768; \
        uint32_t Bd = Ad + 16384; \
        const __nv_bfloat16* Ap = A + (size_t)m0 * KP + (c) * 64; \
        const __nv_bfloat16* Bp = B + (size_t)n0 * KP + (c) * 64; \
        _Pragma("unroll") \
        for (int i = 0; i < 4; i++) { \
            int pos = tid + i * 256; \
            int row = pos >> 3, ch = pos & 7; \
            int sw = ch ^ (row & 7); \
            cpa16(Ad + row * 128 + sw * 16, Ap + (size_t)row * KP + ch * 8); \
            cpa16(Bd + row * 128 + sw * 16, Bp + (size_t)row * KP + ch * 8); \
        } \
    } while (0)

    LOAD_STAGE(0, 0); CP_COMMIT;
    LOAD_STAGE(1, 1); CP_COMMIT;
    LOAD_STAGE(2, 2); CP_COMMIT;

    const int row_in = (lane & 7) + ((lane >> 3) & 1) * 8;
    const int choff = (lane >> 4);

    for (int c = 0; c < KI; c++) {
        CP_WAIT2;
        __syncthreads();
        const int s = c % 3;
        const uint32_t Ab = sb + s * 32768, Bb = Ab + 16384;
#pragma unroll
        for (int q = 0; q < 4; q++) {
            uint32_t a[4][4], b[2][4];
            const int chq = q * 2 + choff;
#pragma unroll
            for (int fm = 0; fm < 4; fm++) {
                int r = wm + fm * 16 + row_in;
                ldsm4(a[fm], Ab + r * 128 + ((chq ^ (r & 7)) * 16));
            }
#pragma unroll
            for (int f2 = 0; f2 < 2; f2++) {
                int r = wn + f2 * 16 + row_in;
                ldsm4(b[f2], Bb + r * 128 + ((chq ^ (r & 7)) * 16));
            }
#pragma unroll
            for (int fm = 0; fm < 4; fm++)
#pragma unroll
                for (int fn = 0; fn < 4; fn++) {
                    uint32_t bb[2] = { b[fn >> 1][fn & 1], b[fn >> 1][(fn & 1) + 2] };
                    mma16816(acc[fm][fn], a[fm], bb);
                }
        }
        __syncthreads();
        if (c + 3 < KI) LOAD_STAGE(s, c + 3);
        CP_COMMIT;
    }

    // ---- epilogue ----
    const int rbase = m0 + wm + (lane >> 2);
    const int cbase = n0 + wn + (lane & 3) * 2;
#pragma unroll
    for (int fm = 0; fm < 4; fm++) {
#pragma unroll
        for (int fn = 0; fn < 4; fn++) {
            const int col = cbase + fn * 8;
#pragma unroll
            for (int half = 0; half < 2; half++) {
                const int row = rbase + fm * 16 + half * 8;
                float v0 = acc[fm][fn][half * 2 + 0];
                float v1 = acc[fm][fn][half * 2 + 1];
                if (MODE >= 1) {
                    float2 bb = *(const float2*)(bias + col);
                    v0 += bb.x; v1 += bb.y;
                }
                if (MODE == 1) {
                    float2 rr = *(const float2*)(resid + (size_t)row * Cc + col);
                    v0 += rr.x; v1 += rr.y;
                    wr_splitA(Cs, (size_t)row * KP + col, v0, v1);
                } else {
                    float2 ov; ov.x = v0; ov.y = v1;
                    *(float2*)(Cf + (size_t)row * N + col) = ov;
                }
            }
        }
    }
#undef LOAD_STAGE
}

// ====================== attention (fp32 SIMT) ======================
__global__ void k_score(const float* __restrict__ qkv, float* __restrict__ probs) {
    __shared__ float As[8][128];
    __shared__ float Bs[8][128];
    const int tid = threadIdx.x;
    const int bh = blockIdx.z;
    const int b = bh >> 3, h = bh & 7;
    const float* Aq = qkv + (size_t)b * Sq * QKV_N + h * DHd;
    const float* Bk = Aq + Cc;
    float* Cp = probs + (size_t)bh * Sq * Sq;
    const int m0 = blockIdx.y * 128, n0 = blockIdx.x * 128;
    const int arow = tid >> 1, acol = (tid & 1) * 4;
    const int tx = tid & 15, ty = tid >> 4;

    float acc[8][8] = {};
    const float* Ap = Aq + (size_t)(m0 + arow) * QKV_N + acol;
    const float* Bp = Bk + (size_t)(n0 + arow) * QKV_N + acol;

    for (int kk = 0; kk < DHd; kk += 8) {
        float4 av = *(const float4*)(Ap + kk);
        As[acol + 0][arow] = av.x; As[acol + 1][arow] = av.y;
        As[acol + 2][arow] = av.z; As[acol + 3][arow] = av.w;
        float4 bv = *(const float4*)(Bp + kk);
        Bs[acol + 0][arow] = bv.x; Bs[acol + 1][arow] = bv.y;
        Bs[acol + 2][arow] = bv.z; Bs[acol + 3][arow] = bv.w;
        __syncthreads();
#pragma unroll
        for (int k = 0; k < 8; k++) {
            float a[8], b2[8];
            *(float4*)(a) = *(const float4*)&As[k][ty * 8];
            *(float4*)(a + 4) = *(const float4*)&As[k][ty * 8 + 4];
            *(float4*)(b2) = *(const float4*)&Bs[k][tx * 8];
            *(float4*)(b2 + 4) = *(const float4*)&Bs[k][tx * 8 + 4];
#pragma unroll
            for (int i = 0; i < 8; i++)
#pragma unroll
                for (int j = 0; j < 8; j++) acc[i][j] = fmaf(a[i], b2[j], acc[i][j]);
        }
        __syncthreads();
    }

    const float scale = 0.07905694150420949f;
#pragma unroll
    for (int i = 0; i < 8; i++) {
        float* cp = Cp + (size_t)(m0 + ty * 8 + i) * Sq + n0 + tx * 8;
#pragma unroll
        for (int j = 0; j < 8; j += 4) {
            float4 v;
            v.x = acc[i][j + 0] * scale; v.y = acc[i][j + 1] * scale;
            v.z = acc[i][j + 2] * scale; v.w = acc[i][j + 3] * scale;
            *(float4*)(cp + j) = v;
        }
    }
}

__global__ void k_softmax(float* __restrict__ probs) {
    __shared__ float red[8];
    const size_t row = blockIdx.x;
    float* p = probs + row * (size_t)Sq;
    const int t = threadIdx.x;
    float4 v = *(float4*)(p + t * 4);

    float m = fmaxf(fmaxf(v.x, v.y), fmaxf(v.z, v.w));
#pragma unroll
    for (int o = 16; o; o >>= 1) m = fmaxf(m, __shfl_xor_sync(0xffffffffu, m, o));
    if ((t & 31) == 0) red[t >> 5] = m;
    __syncthreads();
    m = red[0];
#pragma unroll
    for (int i = 1; i < 8; i++) m = fmaxf(m, red[i]);
    __syncthreads();

    v.x = expf(v.x - m); v.y = expf(v.y - m); v.z = expf(v.z - m); v.w = expf(v.w - m);
    float s = v.x + v.y + v.z + v.w;
#pragma unroll
    for (int o = 16; o; o >>= 1) s += __shfl_xor_sync(0xffffffffu, s, o);
    if ((t & 31) == 0) red[t >> 5] = s;
    __syncthreads();
    s = 0.f;
#pragma unroll
    for (int i = 0; i < 8; i++) s += red[i];
    float inv = 1.0f / s;
    v.x *= inv; v.y *= inv; v.z *= inv; v.w *= inv;
    *(float4*)(p + t * 4) = v;
}

__global__ void k_av(const float* __restrict__ probs, const float* __restrict__ qkv,
                     __nv_bfloat16* __restrict__ O2) {
    __shared__ float As[16][64];
    __shared__ float Bs[16][64];
    const int tid = threadIdx.x;
    const int bh = blockIdx.z;
    const int b = bh >> 3, h = bh & 7;
    const float* P = probs + (size_t)bh * Sq * Sq;
    const float* V = qkv + (size_t)b * Sq * QKV_N + 2 * Cc + h * DHd;
    const int m0 = blockIdx.y * 64, n0 = blockIdx.x * 64;
    const int arow = tid >> 2, acol = (tid & 3) * 4;
    const int brow = tid >> 4, bcol = (tid & 15) * 4;
    const bool bvalid = (n0 + bcol) < DHd;
    const int tx = tid & 15, ty = tid >> 4;

    float acc[4][4] = {};
    for (int kk = 0; kk < Sq; kk += 16) {
        float4 av = *(const float4*)(P + (size_t)(m0 + arow) * Sq + kk + acol);
        As[acol + 0][arow] = av.x; As[acol + 1][arow] = av.y;
        As[acol + 2][arow] = av.z; As[acol + 3][arow] = av.w;
        float4 bv = make_float4(0.f, 0.f, 0.f, 0.f);
        if (bvalid) bv = *(const float4*)(V + (size_t)(kk + brow) * QKV_N + n0 + bcol);
        *(float4*)&Bs[brow][bcol] = bv;
        __syncthreads();
#pragma unroll
        for (int k = 0; k < 16; k++) {
            float a[4], b2[4];
            *(float4*)(a) = *(const float4*)&As[k][ty * 4];
            *(float4*)(b2) = *(const float4*)&Bs[k][tx * 4];
#pragma unroll
            for (int i = 0; i < 4; i++)
#pragma unroll
                for (int j = 0; j < 4; j++) acc[i][j] = fmaf(a[i], b2[j], acc[i][j]);
        }
        __syncthreads();
    }

    const int dbase = n0 + tx * 4;
    if (dbase < DHd) {
#pragma unroll
        for (int i = 0; i < 4; i++) {
            size_t base = (size_t)(b * Sq + m0 + ty * 4 + i) * KP + h * DHd + dbase;
            wr_splitA(O2, base, acc[i][0], acc[i][1]);
            wr_splitA(O2, base + 2, acc[i][2], acc[i][3]);
        }
    }
}

// ====================== launch ======================
#define GEMM_SMEM (3 * 32768)

extern "C" void kernel_launch(void* const* d_in, const int* in_sizes, int n_in,
                              void* d_out, int out_size) {
    const float* h  = (const float*)d_in[0];
    const float* p  = (const float*)d_in[1];
    const float* Wm = (const float*)d_in[2];
    const float* bm = (const float*)d_in[3];
    const float* wq = (const float*)d_in[4];
    const float* wk = (const float*)d_in[5];
    const float* wv = (const float*)d_in[6];
    const float* wo = (const float*)d_in[7];
    const float* bo = (const float*)d_in[8];
    const float* qd = (const float*)d_in[9];
    const float* qu = (const float*)d_in[10];
    const float* kd = (const float*)d_in[11];
    const float* ku = (const float*)d_in[12];
    const float* vd = (const float*)d_in[13];
    const float* vu = (const float*)d_in[14];
    const float* od = (const float*)d_in[15];
    const float* ou = (const float*)d_in[16];

    __nv_bfloat16 *hp2, *x2, *at2, *wm2, *we2, *wo2;
    float *qkv, *probs;
    cudaGetSymbolAddress((void**)&hp2, g_hp2);
    cudaGetSymbolAddress((void**)&x2, g_x2);
    cudaGetSymbolAddress((void**)&at2, g_at2);
    cudaGetSymbolAddress((void**)&wm2, g_wm2);
    cudaGetSymbolAddress((void**)&we2, g_we2);
    cudaGetSymbolAddress((void**)&wo2, g_wo2);
    cudaGetSymbolAddress((void**)&qkv, g_qkv);
    cudaGetSymbolAddress((void**)&probs, g_probs);

    cudaFuncSetAttribute(k_mma<0>, cudaFuncAttributeMaxDynamicSharedMemorySize, GEMM_SMEM);
    cudaFuncSetAttribute(k_mma<1>, cudaFuncAttributeMaxDynamicSharedMemorySize, GEMM_SMEM);
    cudaFuncSetAttribute(k_mma<2>, cudaFuncAttributeMaxDynamicSharedMemorySize, GEMM_SMEM);

    // 1) hp' = split(h + pose)
    int n1 = Mrows * Cc;
    k_add_split<<<(n1 + 255) / 256, 256>>>(h, p, hp2, n1);

    // 2) weight prep (transpose + LoRA fold + split)
    int gw = (Cc * Cc + 255) / 256;
    k_wT_split<<<gw, 256>>>(Wm, nullptr, nullptr, wm2, 0);
    k_wT_split<<<gw, 256>>>(wq, qd, qu, we2, 0);
    k_wT_split<<<gw, 256>>>(wk, kd, ku, we2, Cc);
    k_wT_split<<<gw, 256>>>(wv, vd, vu, we2, 2 * Cc);
    k_wT_split<<<gw, 256>>>(wo, od, ou, wo2, 0);

    // 3) x = hp @ Wm + bm + h  -> split x'
    k_mma<1><<<dim3(Cc / 128, Mrows / 128), 256, GEMM_SMEM>>>(
        hp2, wm2, Cc, nullptr, x2, bm, h);

    // 4) qkv = x @ [Wq|Wk|Wv] (fp32)
    k_mma<0><<<dim3(QKV_N / 128, Mrows / 128), 256, GEMM_SMEM>>>(
        x2, we2, QKV_N, qkv, nullptr, nullptr, nullptr);

    // 5) attention (fp32)
    k_score<<<dim3(Sq / 128, Sq / 128, Bz * Hh), 256>>>(qkv, probs);
    k_softmax<<<Bz * Hh * Sq, 256>>>(probs);
    k_av<<<dim3(3, Sq / 64, Bz * Hh), 256>>>(probs, qkv, at2);

    // 6) out = attn @ Wo + bo (fp32 to d_out)
    k_mma<2><<<dim3(Cc / 128, Mrows / 128), 256, GEMM_SMEM>>>(
        at2, wo2, Cc, (float*)d_out, nullptr, bo, nullptr);
}

// round 5
// speedup vs baseline: 2.2644x; 1.3333x over previous
#include <cuda_runtime.h>
#include <cuda_bf16.h>
#include <cstdint>
#include <math.h>

#define Bz 8
#define Sq 1024
#define Cc 1280
#define Hh 8
#define DHd 160
#define RK 4
#define Mrows (Bz*Sq)      /* 8192 */
#define QKV_N (3*Cc)       /* 3840 */
#define KP (3*Cc)          /* K' = 3840 for dense GEMMs */
#define BH (Bz*Hh)         /* 64 */
#define QKD 512            /* per-head split K (480 data + 32 pad) */
#define PVK 3072           /* P' split K = 3*1024 */
#define VND 192            /* dh padded for PV B tile */

// ====================== helpers ======================
__device__ __forceinline__ uint32_t smem_u32(const void* p) {
    uint32_t a;
    asm("{ .reg .u64 t; cvta.to.shared.u64 t, %1; cvt.u32.u64 %0, t; }" : "=r"(a) : "l"(p));
    return a;
}
__device__ __forceinline__ void cpa16(uint32_t dst, const void* src) {
    asm volatile("cp.async.cg.shared.global [%0], [%1], 16;" :: "r"(dst), "l"(src) : "memory");
}
#define CP_COMMIT asm volatile("cp.async.commit_group;" ::: "memory")
#define CP_WAIT2  asm volatile("cp.async.wait_group 2;" ::: "memory")

__device__ __forceinline__ void ldsm4(uint32_t* r, uint32_t addr) {
    asm volatile("ldmatrix.sync.aligned.m8n8.x4.shared.b16 {%0,%1,%2,%3}, [%4];"
                 : "=r"(r[0]), "=r"(r[1]), "=r"(r[2]), "=r"(r[3]) : "r"(addr));
}
__device__ __forceinline__ void mma16816(float* d, const uint32_t* a, const uint32_t* b) {
    asm volatile(
        "mma.sync.aligned.m16n8k16.row.col.f32.bf16.bf16.f32 "
        "{%0,%1,%2,%3}, {%4,%5,%6,%7}, {%8,%9}, {%0,%1,%2,%3};"
        : "+f"(d[0]), "+f"(d[1]), "+f"(d[2]), "+f"(d[3])
        : "r"(a[0]), "r"(a[1]), "r"(a[2]), "r"(a[3]), "r"(b[0]), "r"(b[1]));
}
__device__ __forceinline__ void split_bf(float v, __nv_bfloat16& h, __nv_bfloat16& l) {
    h = __float2bfloat16(v);
    l = __float2bfloat16(v - __bfloat162float(h));
}
__device__ __forceinline__ void pack_split2(float v0, float v1, uint32_t& uh, uint32_t& ul) {
    __nv_bfloat16 h0, l0, h1, l1;
    split_bf(v0, h0, l0);
    split_bf(v1, h1, l1);
    __nv_bfloat162 hh, ll;
    hh.x = h0; hh.y = h1; ll.x = l0; ll.y = l1;
    uh = *(uint32_t*)&hh; ul = *(uint32_t*)&ll;
}
// write split activation pair into [hi|lo|hi] layout with stride `seg` (A-side)
__device__ __forceinline__ void wr_split(__nv_bfloat16* Cs, size_t base, int seg,
                                         float v0, float v1) {
    uint32_t uh, ul;
    pack_split2(v0, v1, uh, ul);
    *(uint32_t*)(Cs + base)           = uh;
    *(uint32_t*)(Cs + base + seg)     = ul;
    *(uint32_t*)(Cs + base + 2 * seg) = uh;
}

// ====================== scratch ======================
__device__ __nv_bfloat16 g_hp2[(size_t)Mrows * KP];
__device__ __nv_bfloat16 g_x2[(size_t)Mrows * KP];
__device__ __nv_bfloat16 g_at2[(size_t)Mrows * KP];
__device__ __nv_bfloat16 g_wm2[(size_t)Cc * KP];
__device__ __nv_bfloat16 g_we2[(size_t)QKV_N * KP];
__device__ __nv_bfloat16 g_wo2[(size_t)Cc * KP];
__device__ float g_qkv[(size_t)Mrows * QKV_N];
__device__ float g_scores[(size_t)BH * Sq * Sq];
__device__ __nv_bfloat16 g_q2[(size_t)BH * Sq * QKD];
__device__ __nv_bfloat16 g_k2[(size_t)BH * Sq * QKD];
__device__ __nv_bfloat16 g_p2[(size_t)BH * Sq * PVK];
__device__ __nv_bfloat16 g_v2t[(size_t)BH * VND * PVK];

// ====================== prep kernels ======================
__global__ void k_add_split(const float* __restrict__ a, const float* __restrict__ b,
                            __nv_bfloat16* __restrict__ dst) {
    int i = blockIdx.x * 256 + threadIdx.x;       // pair index
    if (i >= Mrows * Cc / 2) return;
    int row = i / (Cc / 2), kp = (i - row * (Cc / 2)) * 2;
    int gi = row * Cc + kp;
    float v0 = a[gi] + b[gi], v1 = a[gi + 1] + b[gi + 1];
    wr_split(dst, (size_t)row * KP + kp, Cc, v0, v1);
}

// tiled weight transpose + LoRA fold + split (B-side [hi|hi|lo])
__global__ void k_wT(const float* __restrict__ W, const float* __restrict__ dn,
                     const float* __restrict__ up, __nv_bfloat16* __restrict__ dst,
                     int dstoff) {
    __shared__ float t[32][33];
    const int tid = threadIdx.x;
    const int k0 = blockIdx.y * 32, n0 = blockIdx.x * 32;
#pragma unroll
    for (int j = 0; j < 4; j++) {
        int idx = tid + j * 256;
        int kr = idx >> 5, nc = idx & 31;
        float s = W[(size_t)(k0 + kr) * Cc + n0 + nc];
        if (dn != nullptr) {
#pragma unroll
            for (int r = 0; r < RK; r++)
                s += dn[(k0 + kr) * RK + r] * up[r * Cc + n0 + nc];
        }
        t[kr][nc] = s;
    }
    __syncthreads();
#pragma unroll
    for (int j = 0; j < 2; j++) {
        int idx = tid + j * 256;
        int nr = idx >> 4, kc = (idx & 15) * 2;
        float v0 = t[kc][nr], v1 = t[kc + 1][nr];
        uint32_t uh, ul;
        pack_split2(v0, v1, uh, ul);
        size_t base = (size_t)(dstoff + n0 + nr) * KP + k0 + kc;
        *(uint32_t*)(dst + base)          = uh;
        *(uint32_t*)(dst + base + Cc)     = uh;
        *(uint32_t*)(dst + base + 2 * Cc) = ul;
    }
}

// build q2 (A-side [hi|lo|hi]) and k2 (B-side [hi|hi|lo]); pad to QKD with zeros
__global__ void k_qk(const float* __restrict__ qkv, __nv_bfloat16* __restrict__ q2,
                     __nv_bfloat16* __restrict__ k2) {
    size_t i = (size_t)blockIdx.x * 256 + threadIdx.x;
    const size_t half = (size_t)BH * Sq * DHd;
    if (i >= 2 * half) return;
    int which = (i >= half);     // 0 = Q (A-side), 1 = K (B-side)
    size_t j = which ? i - half : i;
    int d = (int)(j % DHd);
    size_t t = j / DHd;
    int s = (int)(t % Sq);
    int bh = (int)(t / Sq);
    int b = bh >> 3, h = bh & 7;
    float v = qkv[((size_t)b * Sq + s) * QKV_N + which * Cc + h * DHd + d];
    __nv_bfloat16 hi, lo;
    split_bf(v, hi, lo);
    __nv_bfloat16* dst = (which ? k2 : q2) + ((size_t)bh * Sq + s) * QKD;
    dst[d] = hi;
    dst[DHd + d]     = which ? hi : lo;   // B-side: hi, A-side: lo
    dst[2 * DHd + d] = which ? lo : hi;   // B-side: lo, A-side: hi
    if (d < QKD - 3 * DHd) dst[3 * DHd + d] = __float2bfloat16(0.f);
}

// build v2t (B-side [hi|hi|lo] along PVK): [bh][d(0..191)][Vhi(0:1024)|Vhi|Vlo]
__global__ void k_vT(const float* __restrict__ qkv, __nv_bfloat16* __restrict__ v2t) {
    __shared__ float t[32][33];
    const int tid = threadIdx.x;
    const int bh = blockIdx.z, b = bh >> 3, h = bh & 7;
    const int s0 = blockIdx.y * 32, d0 = blockIdx.x * 32;
#pragma unroll
    for (int j = 0; j < 4; j++) {
        int idx = tid + j * 256;
        int sr = idx >> 5, dc = idx & 31;
        float v = 0.f;
        if (d0 + dc < DHd)
            v = qkv[((size_t)b * Sq + s0 + sr) * QKV_N + 2 * Cc + h * DHd + d0 + dc];
        t[sr][dc] = v;
    }
    __syncthreads();
#pragma unroll
    for (int j = 0; j < 2; j++) {
        int idx = tid + j * 256;
        int dr = idx >> 4, sc = (idx & 15) * 2;
        float v0 = t[sc][dr], v1 = t[sc + 1][dr];
        uint32_t uh, ul;
        pack_split2(v0, v1, uh, ul);
        size_t base = (size_t)bh * VND * PVK + (size_t)(d0 + dr) * PVK + s0 + sc;
        *(uint32_t*)(v2t + base)        = uh;
        *(uint32_t*)(v2t + base + Sq)   = uh;
        *(uint32_t*)(v2t + base + 2*Sq) = ul;
    }
}

// ====================== generic HMMA GEMM ======================
// C[M,N] = A'[M,lda] @ B'[N,ldb]^T, 128x128 CTA tile, 8 warps, 3-stage cp.async.
// MODE 0: fp32 out. MODE 1: +bias+resid, split write (dense). MODE 2: +bias, fp32.
// MODE 3: *scale, fp32 out (scores).
template <int MODE>
__global__ void __launch_bounds__(256, 1) k_mma(
    const __nv_bfloat16* __restrict__ A, const __nv_bfloat16* __restrict__ B,
    float* __restrict__ Cf, __nv_bfloat16* __restrict__ Cs,
    const float* __restrict__ bias, const float* __restrict__ resid,
    int lda, int ldb, int KI, int N, size_t sA, size_t sB, size_t sC) {
    extern __shared__ char sm[];
    const uint32_t sb = smem_u32(sm);
    const int tid = threadIdx.x, lane = tid & 31, wid = tid >> 5;
    const int m0 = blockIdx.y * 128, n0 = blockIdx.x * 128;
    const int wm = (wid >> 2) * 64, wn = (wid & 3) * 32;
    const int z = blockIdx.z;
    A += (size_t)z * sA;
    B += (size_t)z * sB;

    float acc[4][4][4] = {};

#define LOAD_STAGE(s, c) do { \
        uint32_t Ad = sb + (s) * 32768; \
        uint32_t Bd = Ad + 16384; \
        const __nv_bfloat16* Ap = A + (size_t)m0 * lda + (c) * 64; \
        const __nv_bfloat16* Bp = B + (size_t)n0 * ldb + (c) * 64; \
        _Pragma("unroll") \
        for (int i = 0; i < 4; i++) { \
            int pos = tid + i * 256; \
            int row = pos >> 3, ch = pos & 7; \
            int sw = ch ^ (row & 7); \
            cpa16(Ad + row * 128 + sw * 16, Ap + (size_t)row * lda + ch * 8); \
            cpa16(Bd + row * 128 + sw * 16, Bp + (size_t)row * ldb + ch * 8); \
        } \
    } while (0)

    LOAD_STAGE(0, 0); CP_COMMIT;
    LOAD_STAGE(1, 1); CP_COMMIT;
    LOAD_STAGE(2, 2); CP_COMMIT;

    const int row_in = (lane & 7) + ((lane >> 3) & 1) * 8;
    const int choff = (lane >> 4);

    for (int c = 0; c < KI; c++) {
        CP_WAIT2;
        __syncthreads();
        const int s = c % 3;
        const uint32_t Ab = sb + s * 32768, Bb = Ab + 16384;
#pragma unroll
        for (int q = 0; q < 4; q++) {
            uint32_t a[4][4], b[2][4];
            const int chq = q * 2 + choff;
#pragma unroll
            for (int fm = 0; fm < 4; fm++) {
                int r = wm + fm * 16 + row_in;
                ldsm4(a[fm], Ab + r * 128 + ((chq ^ (r & 7)) * 16));
            }
#pragma unroll
            for (int f2 = 0; f2 < 2; f2++) {
                int r = wn + f2 * 16 + row_in;
                ldsm4(b[f2], Bb + r * 128 + ((chq ^ (r & 7)) * 16));
            }
#pragma unroll
            for (int fm = 0; fm < 4; fm++)
#pragma unroll
                for (int fn = 0; fn < 4; fn++) {
                    uint32_t bb[2] = { b[fn >> 1][fn & 1], b[fn >> 1][(fn & 1) + 2] };
                    mma16816(acc[fm][fn], a[fm], bb);
                }
        }
        __syncthreads();
        if (c + 3 < KI) LOAD_STAGE(s, c + 3);
        CP_COMMIT;
    }
#undef LOAD_STAGE

    const int rbase = m0 + wm + (lane >> 2);
    const int cbase = n0 + wn + (lane & 3) * 2;
#pragma unroll
    for (int fm = 0; fm < 4; fm++) {
#pragma unroll
        for (int fn = 0; fn < 4; fn++) {
            const int col = cbase + fn * 8;
#pragma unroll
            for (int half = 0; half < 2; half++) {
                const int row = rbase + fm * 16 + half * 8;
                float v0 = acc[fm][fn][half * 2 + 0];
                float v1 = acc[fm][fn][half * 2 + 1];
                if (MODE == 1 || MODE == 2) {
                    float2 bb = *(const float2*)(bias + col);
                    v0 += bb.x; v1 += bb.y;
                }
                if (MODE == 1) {
                    float2 rr = *(const float2*)(resid + (size_t)row * Cc + col);
                    v0 += rr.x; v1 += rr.y;
                    wr_split(Cs, (size_t)row * KP + col, Cc, v0, v1);
                } else if (MODE == 3) {
                    const float scale = 0.07905694150420949f;
                    float2 ov; ov.x = v0 * scale; ov.y = v1 * scale;
                    *(float2*)(Cf + (size_t)z * sC + (size_t)row * N + col) = ov;
                } else {
                    float2 ov; ov.x = v0; ov.y = v1;
                    *(float2*)(Cf + (size_t)row * N + col) = ov;
                }
            }
        }
    }
}

// ====================== softmax: fp32 scores -> split P' (A-side) ======================
__global__ void k_softmax2(const float* __restrict__ scores, __nv_bfloat16* __restrict__ p2) {
    __shared__ float red[8];
    const size_t row = blockIdx.x;
    const float* p = scores + row * (size_t)Sq;
    __nv_bfloat16* o = p2 + row * (size_t)PVK;
    const int t = threadIdx.x;
    float4 v = *(const float4*)(p + t * 4);

    float m = fmaxf(fmaxf(v.x, v.y), fmaxf(v.z, v.w));
#pragma unroll
    for (int off = 16; off; off >>= 1) m = fmaxf(m, __shfl_xor_sync(0xffffffffu, m, off));
    if ((t & 31) == 0) red[t >> 5] = m;
    __syncthreads();
    m = red[0];
#pragma unroll
    for (int i = 1; i < 8; i++) m = fmaxf(m, red[i]);
    __syncthreads();

    v.x = expf(v.x - m); v.y = expf(v.y - m); v.z = expf(v.z - m); v.w = expf(v.w - m);
    float s = v.x + v.y + v.z + v.w;
#pragma unroll
    for (int off = 16; off; off >>= 1) s += __shfl_xor_sync(0xffffffffu, s, off);
    if ((t & 31) == 0) red[t >> 5] = s;
    __syncthreads();
    s = 0.f;
#pragma unroll
    for (int i = 0; i < 8; i++) s += red[i];
    float inv = 1.0f / s;
    v.x *= inv; v.y *= inv; v.z *= inv; v.w *= inv;

    uint32_t uh0, ul0, uh1, ul1;
    pack_split2(v.x, v.y, uh0, ul0);
    pack_split2(v.z, v.w, uh1, ul1);
    uint2 uh; uh.x = uh0; uh.y = uh1;
    uint2 ul; ul.x = ul0; ul.y = ul1;
    *(uint2*)(o + t * 4)            = uh;   // Phi
    *(uint2*)(o + Sq + t * 4)       = ul;   // Plo
    *(uint2*)(o + 2 * Sq + t * 4)   = uh;   // Phi
}

// ====================== PV GEMM: out[s, dh] = P' @ V'^T ======================
// CTA tile 128(M) x 192(N), 8 warps = 2(M) x 4(N) -> warp tile 64x48. KI = 48.
__global__ void __launch_bounds__(256, 1) k_pv(
    const __nv_bfloat16* __restrict__ P, const __nv_bfloat16* __restrict__ V,
    __nv_bfloat16* __restrict__ at2) {
    extern __shared__ char sm[];
    const uint32_t sb = smem_u32(sm);
    const int tid = threadIdx.x, lane = tid & 31, wid = tid >> 5;
    const int bh = blockIdx.z, b = bh >> 3, h = bh & 7;
    const int m0 = blockIdx.y * 128;
    const int wm = (wid >> 2) * 64, wn = (wid & 3) * 48;
    const __nv_bfloat16* A = P + (size_t)bh * Sq * PVK;
    const __nv_bfloat16* Bp0 = V + (size_t)bh * VND * PVK;

    float acc[4][6][4] = {};

#define LOAD_PV(s, c) do { \
        uint32_t Ad = sb + (s) * 40960; \
        uint32_t Bd = Ad + 16384; \
        const __nv_bfloat16* Ap = A + (size_t)m0 * PVK + (c) * 64; \
        const __nv_bfloat16* Bp = Bp0 + (c) * 64; \
        _Pragma("unroll") \
        for (int i = 0; i < 4; i++) { \
            int pos = tid + i * 256; \
            int row = pos >> 3, ch = pos & 7; \
            int sw = ch ^ (row & 7); \
            cpa16(Ad + row * 128 + sw * 16, Ap + (size_t)row * PVK + ch * 8); \
        } \
        _Pragma("unroll") \
        for (int i = 0; i < 6; i++) { \
            int pos = tid + i * 256; \
            int row = pos >> 3, ch = pos & 7; \
            int sw = ch ^ (row & 7); \
            cpa16(Bd + row * 128 + sw * 16, Bp + (size_t)row * PVK + ch * 8); \
        } \
    } while (0)

    LOAD_PV(0, 0); CP_COMMIT;
    LOAD_PV(1, 1); CP_COMMIT;
    LOAD_PV(2, 2); CP_COMMIT;

    const int row_in = (lane & 7) + ((lane >> 3) & 1) * 8;
    const int choff = (lane >> 4);
    const int KI = PVK / 64;   // 48

    for (int c = 0; c < KI; c++) {
        CP_WAIT2;
        __syncthreads();
        const int s = c % 3;
        const uint32_t Ab = sb + s * 40960, Bb = Ab + 16384;
#pragma unroll
        for (int q = 0; q < 4; q++) {
            uint32_t a[4][4], b[3][4];
            const int chq = q * 2 + choff;
#pragma unroll
            for (int fm = 0; fm < 4; fm++) {
                int r = wm + fm * 16 + row_in;
                ldsm4(a[fm], Ab + r * 128 + ((chq ^ (r & 7)) * 16));
            }
#pragma unroll
            for (int f2 = 0; f2 < 3; f2++) {
                int r = wn + f2 * 16 + row_in;
                ldsm4(b[f2], Bb + r * 128 + ((chq ^ (r & 7)) * 16));
            }
#pragma unroll
            for (int fm = 0; fm < 4; fm++)
#pragma unroll
                for (int fn = 0; fn < 6; fn++) {
                    uint32_t bb[2] = { b[fn >> 1][fn & 1], b[fn >> 1][(fn & 1) + 2] };
                    mma16816(acc[fm][fn], a[fm], bb);
                }
        }
        __syncthreads();
        if (c + 3 < KI) LOAD_PV(s, c + 3);
        CP_COMMIT;
    }
#undef LOAD_PV

    // epilogue: write split A' for the output projection; cols >= 160 discarded
    const int rbase = m0 + wm + (lane >> 2);
    const int cbase = wn + (lane & 3) * 2;
#pragma unroll
    for (int fm = 0; fm < 4; fm++) {
#pragma unroll
        for (int fn = 0; fn < 6; fn++) {
            const int col = cbase + fn * 8;
            if (col >= DHd) continue;
#pragma unroll
            for (int half = 0; half < 2; half++) {
                const int srow = rbase + fm * 16 + half * 8;
                size_t base = ((size_t)b * Sq + srow) * KP + h * DHd + col;
                wr_split(at2, base, Cc, acc[fm][fn][half * 2 + 0], acc[fm][fn][half * 2 + 1]);
            }
        }
    }
}

// ====================== launch ======================
#define GEMM_SMEM (3 * 32768)
#define PV_SMEM   (3 * 40960)

extern "C" void kernel_launch(void* const* d_in, const int* in_sizes, int n_in,
                              void* d_out, int out_size) {
    const float* h  = (const float*)d_in[0];
    const float* p  = (const float*)d_in[1];
    const float* Wm = (const float*)d_in[2];
    const float* bm = (const float*)d_in[3];
    const float* wq = (const float*)d_in[4];
    const float* wk = (const float*)d_in[5];
    const float* wv = (const float*)d_in[6];
    const float* wo = (const float*)d_in[7];
    const float* bo = (const float*)d_in[8];
    const float* qd = (const float*)d_in[9];
    const float* qu = (const float*)d_in[10];
    const float* kd = (const float*)d_in[11];
    const float* ku = (const float*)d_in[12];
    const float* vd = (const float*)d_in[13];
    const float* vu = (const float*)d_in[14];
    const float* od = (const float*)d_in[15];
    const float* ou = (const float*)d_in[16];

    __nv_bfloat16 *hp2, *x2, *at2, *wm2, *we2, *wo2, *q2, *k2, *p2, *v2t;
    float *qkv, *scores;
    cudaGetSymbolAddress((void**)&hp2, g_hp2);
    cudaGetSymbolAddress((void**)&x2, g_x2);
    cudaGetSymbolAddress((void**)&at2, g_at2);
    cudaGetSymbolAddress((void**)&wm2, g_wm2);
    cudaGetSymbolAddress((void**)&we2, g_we2);
    cudaGetSymbolAddress((void**)&wo2, g_wo2);
    cudaGetSymbolAddress((void**)&qkv, g_qkv);
    cudaGetSymbolAddress((void**)&scores, g_scores);
    cudaGetSymbolAddress((void**)&q2, g_q2);
    cudaGetSymbolAddress((void**)&k2, g_k2);
    cudaGetSymbolAddress((void**)&p2, g_p2);
    cudaGetSymbolAddress((void**)&v2t, g_v2t);

    cudaFuncSetAttribute(k_mma<0>, cudaFuncAttributeMaxDynamicSharedMemorySize, GEMM_SMEM);
    cudaFuncSetAttribute(k_mma<1>, cudaFuncAttributeMaxDynamicSharedMemorySize, GEMM_SMEM);
    cudaFuncSetAttribute(k_mma<2>, cudaFuncAttributeMaxDynamicSharedMemorySize, GEMM_SMEM);
    cudaFuncSetAttribute(k_mma<3>, cudaFuncAttributeMaxDynamicSharedMemorySize, GEMM_SMEM);
    cudaFuncSetAttribute(k_pv, cudaFuncAttributeMaxDynamicSharedMemorySize, PV_SMEM);

    // 1) hp' = split(h + pose)
    k_add_split<<<(Mrows * Cc / 2 + 255) / 256, 256>>>(h, p, hp2);

    // 2) weight prep (tiled transpose + LoRA fold + split)
    dim3 gw(Cc / 32, Cc / 32);
    k_wT<<<gw, 256>>>(Wm, nullptr, nullptr, wm2, 0);
    k_wT<<<gw, 256>>>(wq, qd, qu, we2, 0);
    k_wT<<<gw, 256>>>(wk, kd, ku, we2, Cc);
    k_wT<<<gw, 256>>>(wv, vd, vu, we2, 2 * Cc);
    k_wT<<<gw, 256>>>(wo, od, ou, wo2, 0);

    // 3) x = hp @ Wm + bm + h  -> split x'
    k_mma<1><<<dim3(Cc / 128, Mrows / 128, 1), 256, GEMM_SMEM>>>(
        hp2, wm2, nullptr, x2, bm, h, KP, KP, KP / 64, Cc, 0, 0, 0);

    // 4) qkv = x @ [Wq|Wk|Wv] (fp32)
    k_mma<0><<<dim3(QKV_N / 128, Mrows / 128, 1), 256, GEMM_SMEM>>>(
        x2, we2, qkv, nullptr, nullptr, nullptr, KP, KP, KP / 64, QKV_N, 0, 0, 0);

    // 5) attention prep
    {
        size_t tot = 2ull * BH * Sq * DHd;
        k_qk<<<(unsigned)((tot + 255) / 256), 256>>>(qkv, q2, k2);
        k_vT<<<dim3(VND / 32, Sq / 32, BH), 256>>>(qkv, v2t);
    }

    // 6) scores = scale * Q' @ K'^T (fp32)
    k_mma<3><<<dim3(Sq / 128, Sq / 128, BH), 256, GEMM_SMEM>>>(
        q2, k2, scores, nullptr, nullptr, nullptr, QKD, QKD, QKD / 64, Sq,
        (size_t)Sq * QKD, (size_t)Sq * QKD, (size_t)Sq * Sq);

    // 7) softmax -> split P'
    k_softmax2<<<BH * Sq, 256>>>(scores, p2);

    // 8) out_attn = P' @ V'^T -> split at2
    k_pv<<<dim3(1, Sq / 128, BH), 256, PV_SMEM>>>(p2, v2t, at2);

    // 9) out = attn @ Wo + bo (fp32 to d_out)
    k_mma<2><<<dim3(Cc / 128, Mrows / 128, 1), 256, GEMM_SMEM>>>(
        at2, wo2, (float*)d_out, nullptr, bo, nullptr, KP, KP, KP / 64, Cc, 0, 0, 0);
}

// round 6
// speedup vs baseline: 2.4449x; 1.0797x over previous
#include <cuda_runtime.h>
#include <cuda_bf16.h>
#include <cstdint>
#include <math.h>

#define Bz 8
#define Sq 1024
#define Cc 1280
#define Hh 8
#define DHd 160
#define RK 4
#define Mrows (Bz*Sq)      /* 8192 */
#define QKV_N (3*Cc)       /* 3840 */
#define KP (3*Cc)          /* K' = 3840 for dense GEMMs */
#define BH (Bz*Hh)         /* 64 */

// ====================== helpers ======================
__device__ __forceinline__ uint32_t smem_u32(const void* p) {
    uint32_t a;
    asm("{ .reg .u64 t; cvta.to.shared.u64 t, %1; cvt.u32.u64 %0, t; }" : "=r"(a) : "l"(p));
    return a;
}
__device__ __forceinline__ void cpa16(uint32_t dst, const void* src) {
    asm volatile("cp.async.cg.shared.global [%0], [%1], 16;" :: "r"(dst), "l"(src) : "memory");
}
#define CP_COMMIT asm volatile("cp.async.commit_group;" ::: "memory")
#define CP_WAIT0  asm volatile("cp.async.wait_group 0;" ::: "memory")
#define CP_WAIT1  asm volatile("cp.async.wait_group 1;" ::: "memory")
#define CP_WAIT2  asm volatile("cp.async.wait_group 2;" ::: "memory")

__device__ __forceinline__ void ldsm4(uint32_t* r, uint32_t addr) {
    asm volatile("ldmatrix.sync.aligned.m8n8.x4.shared.b16 {%0,%1,%2,%3}, [%4];"
                 : "=r"(r[0]), "=r"(r[1]), "=r"(r[2]), "=r"(r[3]) : "r"(addr));
}
__device__ __forceinline__ void mma16816(float* d, const uint32_t* a, const uint32_t* b) {
    asm volatile(
        "mma.sync.aligned.m16n8k16.row.col.f32.bf16.bf16.f32 "
        "{%0,%1,%2,%3}, {%4,%5,%6,%7}, {%8,%9}, {%0,%1,%2,%3};"
        : "+f"(d[0]), "+f"(d[1]), "+f"(d[2]), "+f"(d[3])
        : "r"(a[0]), "r"(a[1]), "r"(a[2]), "r"(a[3]), "r"(b[0]), "r"(b[1]));
}
__device__ __forceinline__ void split_bf(float v, __nv_bfloat16& h, __nv_bfloat16& l) {
    h = __float2bfloat16(v);
    l = __float2bfloat16(v - __bfloat162float(h));
}
__device__ __forceinline__ void pack_split2(float v0, float v1, uint32_t& uh, uint32_t& ul) {
    __nv_bfloat16 h0, l0, h1, l1;
    split_bf(v0, h0, l0);
    split_bf(v1, h1, l1);
    __nv_bfloat162 hh, ll;
    hh.x = h0; hh.y = h1; ll.x = l0; ll.y = l1;
    uh = *(uint32_t*)&hh; ul = *(uint32_t*)&ll;
}
// write split activation pair into [hi|lo|hi] layout with stride `seg` (A-side)
__device__ __forceinline__ void wr_split(__nv_bfloat16* Cs, size_t base, int seg,
                                         float v0, float v1) {
    uint32_t uh, ul;
    pack_split2(v0, v1, uh, ul);
    *(uint32_t*)(Cs + base)           = uh;
    *(uint32_t*)(Cs + base + seg)     = ul;
    *(uint32_t*)(Cs + base + 2 * seg) = uh;
}
__device__ __forceinline__ uint32_t swz24(int c, int r) { return (c & 24) | ((c & 7) ^ (r & 7)); }
__device__ __forceinline__ uint32_t swz16(int c, int r) { return (c & 8) | ((c & 7) ^ (r & 7)); }

// ====================== scratch ======================
__device__ __nv_bfloat16 g_hp2[(size_t)Mrows * KP];
__device__ __nv_bfloat16 g_x2[(size_t)Mrows * KP];
__device__ __nv_bfloat16 g_at2[(size_t)Mrows * KP];
__device__ __nv_bfloat16 g_wm2[(size_t)Cc * KP];
__device__ __nv_bfloat16 g_we2[(size_t)QKV_N * KP];
__device__ __nv_bfloat16 g_wo2[(size_t)Cc * KP];
__device__ float g_qkv[(size_t)Mrows * QKV_N];
__device__ __nv_bfloat16 g_qc[(size_t)BH * Sq * 320];   // [hi160|lo160]
__device__ __nv_bfloat16 g_kc[(size_t)BH * Sq * 320];   // [hi160|lo160]
__device__ __nv_bfloat16 g_vc[(size_t)BH * DHd * 2048]; // [d][ hi(1024) | lo(1024) ]

// ====================== prep kernels ======================
__global__ void k_add_split(const float* __restrict__ a, const float* __restrict__ b,
                            __nv_bfloat16* __restrict__ dst) {
    int i = blockIdx.x * 256 + threadIdx.x;       // pair index
    if (i >= Mrows * Cc / 2) return;
    int row = i / (Cc / 2), kp = (i - row * (Cc / 2)) * 2;
    int gi = row * Cc + kp;
    float v0 = a[gi] + b[gi], v1 = a[gi + 1] + b[gi + 1];
    wr_split(dst, (size_t)row * KP + kp, Cc, v0, v1);
}

// tiled weight transpose + LoRA fold + split (B-side [hi|hi|lo])
__global__ void k_wT(const float* __restrict__ W, const float* __restrict__ dn,
                     const float* __restrict__ up, __nv_bfloat16* __restrict__ dst,
                     int dstoff) {
    __shared__ float t[32][33];
    const int tid = threadIdx.x;
    const int k0 = blockIdx.y * 32, n0 = blockIdx.x * 32;
#pragma unroll
    for (int j = 0; j < 4; j++) {
        int idx = tid + j * 256;
        int kr = idx >> 5, nc = idx & 31;
        float s = W[(size_t)(k0 + kr) * Cc + n0 + nc];
        if (dn != nullptr) {
#pragma unroll
            for (int r = 0; r < RK; r++)
                s += dn[(k0 + kr) * RK + r] * up[r * Cc + n0 + nc];
        }
        t[kr][nc] = s;
    }
    __syncthreads();
#pragma unroll
    for (int j = 0; j < 2; j++) {
        int idx = tid + j * 256;
        int nr = idx >> 4, kc = (idx & 15) * 2;
        float v0 = t[kc][nr], v1 = t[kc + 1][nr];
        uint32_t uh, ul;
        pack_split2(v0, v1, uh, ul);
        size_t base = (size_t)(dstoff + n0 + nr) * KP + k0 + kc;
        *(uint32_t*)(dst + base)          = uh;
        *(uint32_t*)(dst + base + Cc)     = uh;
        *(uint32_t*)(dst + base + 2 * Cc) = ul;
    }
}

// build compact q/k: [bh][s][hi(160)|lo(160)]
__global__ void k_qc(const float* __restrict__ qkv, __nv_bfloat16* __restrict__ qc,
                     __nv_bfloat16* __restrict__ kc) {
    size_t i = (size_t)blockIdx.x * 256 + threadIdx.x;
    const size_t half = (size_t)BH * Sq * DHd;
    if (i >= 2 * half) return;
    int which = (i >= half);
    size_t j = which ? i - half : i;
    int d = (int)(j % DHd);
    size_t t = j / DHd;
    int s = (int)(t % Sq);
    int bh = (int)(t / Sq);
    int b = bh >> 3, h = bh & 7;
    float v = qkv[((size_t)b * Sq + s) * QKV_N + which * Cc + h * DHd + d];
    __nv_bfloat16 hi, lo;
    split_bf(v, hi, lo);
    __nv_bfloat16* dst = (which ? kc : qc) + ((size_t)bh * Sq + s) * 320;
    dst[d] = hi;
    dst[DHd + d] = lo;
}

// build vc: [bh][d(160)][ hi(0:1024) | lo(1024:2048) ] (transpose)
__global__ void k_vc(const float* __restrict__ qkv, __nv_bfloat16* __restrict__ vc) {
    __shared__ float t[32][33];
    const int tid = threadIdx.x;
    const int bh = blockIdx.z, b = bh >> 3, h = bh & 7;
    const int s0 = blockIdx.y * 32, d0 = blockIdx.x * 32;
#pragma unroll
    for (int j = 0; j < 4; j++) {
        int idx = tid + j * 256;
        int sr = idx >> 5, dc = idx & 31;
        t[sr][dc] = qkv[((size_t)b * Sq + s0 + sr) * QKV_N + 2 * Cc + h * DHd + d0 + dc];
    }
    __syncthreads();
#pragma unroll
    for (int j = 0; j < 2; j++) {
        int idx = tid + j * 256;
        int dr = idx >> 4, sc = (idx & 15) * 2;
        float v0 = t[sc][dr], v1 = t[sc + 1][dr];
        uint32_t uh, ul;
        pack_split2(v0, v1, uh, ul);
        size_t base = (size_t)bh * DHd * 2048 + (size_t)(d0 + dr) * 2048 + s0 + sc;
        *(uint32_t*)(vc + base)        = uh;
        *(uint32_t*)(vc + base + 1024) = ul;
    }
}

// ====================== generic HMMA GEMM (dense projections) ======================
// MODE 0: fp32 out. MODE 1: +bias+resid, split write. MODE 2: +bias, fp32 out.
template <int MODE>
__global__ void __launch_bounds__(256, 1) k_mma(
    const __nv_bfloat16* __restrict__ A, const __nv_bfloat16* __restrict__ B,
    float* __restrict__ Cf, __nv_bfloat16* __restrict__ Cs,
    const float* __restrict__ bias, const float* __restrict__ resid,
    int lda, int ldb, int KI, int N) {
    extern __shared__ char sm[];
    const uint32_t sb = smem_u32(sm);
    const int tid = threadIdx.x, lane = tid & 31, wid = tid >> 5;
    const int m0 = blockIdx.y * 128, n0 = blockIdx.x * 128;
    const int wm = (wid >> 2) * 64, wn = (wid & 3) * 32;

    float acc[4][4][4] = {};

#define LOAD_STAGE(s, c) do { \
        uint32_t Ad = sb + (s) * 32768; \
        uint32_t Bd = Ad + 16384; \
        const __nv_bfloat16* Ap = A + (size_t)m0 * lda + (c) * 64; \
        const __nv_bfloat16* Bp = B + (size_t)n0 * ldb + (c) * 64; \
        _Pragma("unroll") \
        for (int i = 0; i < 4; i++) { \
            int pos = tid + i * 256; \
            int row = pos >> 3, ch = pos & 7; \
            int sw = ch ^ (row & 7); \
            cpa16(Ad + row * 128 + sw * 16, Ap + (size_t)row * lda + ch * 8); \
            cpa16(Bd + row * 128 + sw * 16, Bp + (size_t)row * ldb + ch * 8); \
        } \
    } while (0)

    LOAD_STAGE(0, 0); CP_COMMIT;
    LOAD_STAGE(1, 1); CP_COMMIT;
    LOAD_STAGE(2, 2); CP_COMMIT;

    const int row_in = (lane & 7) + ((lane >> 3) & 1) * 8;
    const int choff = (lane >> 4);

    for (int c = 0; c < KI; c++) {
        CP_WAIT2;
        __syncthreads();
        const int s = c % 3;
        const uint32_t Ab = sb + s * 32768, Bb = Ab + 16384;
#pragma unroll
        for (int q = 0; q < 4; q++) {
            uint32_t a[4][4], b[2][4];
            const int chq = q * 2 + choff;
#pragma unroll
            for (int fm = 0; fm < 4; fm++) {
                int r = wm + fm * 16 + row_in;
                ldsm4(a[fm], Ab + r * 128 + ((chq ^ (r & 7)) * 16));
            }
#pragma unroll
            for (int f2 = 0; f2 < 2; f2++) {
                int r = wn + f2 * 16 + row_in;
                ldsm4(b[f2], Bb + r * 128 + ((chq ^ (r & 7)) * 16));
            }
#pragma unroll
            for (int fm = 0; fm < 4; fm++)
#pragma unroll
                for (int fn = 0; fn < 4; fn++) {
                    uint32_t bb[2] = { b[fn >> 1][fn & 1], b[fn >> 1][(fn & 1) + 2] };
                    mma16816(acc[fm][fn], a[fm], bb);
                }
        }
        __syncthreads();
        if (c + 3 < KI) LOAD_STAGE(s, c + 3);
        CP_COMMIT;
    }
#undef LOAD_STAGE

    const int rbase = m0 + wm + (lane >> 2);
    const int cbase = n0 + wn + (lane & 3) * 2;
#pragma unroll
    for (int fm = 0; fm < 4; fm++) {
#pragma unroll
        for (int fn = 0; fn < 4; fn++) {
            const int col = cbase + fn * 8;
#pragma unroll
            for (int half = 0; half < 2; half++) {
                const int row = rbase + fm * 16 + half * 8;
                float v0 = acc[fm][fn][half * 2 + 0];
                float v1 = acc[fm][fn][half * 2 + 1];
                if (MODE >= 1) {
                    float2 bb = *(const float2*)(bias + col);
                    v0 += bb.x; v1 += bb.y;
                }
                if (MODE == 1) {
                    float2 rr = *(const float2*)(resid + (size_t)row * Cc + col);
                    v0 += rr.x; v1 += rr.y;
                    wr_split(Cs, (size_t)row * KP + col, Cc, v0, v1);
                } else {
                    float2 ov; ov.x = v0; ov.y = v1;
                    *(float2*)(Cf + (size_t)row * N + col) = ov;
                }
            }
        }
    }
}

// ====================== flash attention (split-bf16, fused) ======================
// grid (8 qtiles, 64 bh), 256 threads. Warp w owns q-rows [w*16, w*16+16).
// smem: QLO[128][384B] | KHI[128][384B] | KLO[128][384B] | VHI[160][256B] | VLO[160][256B]
#define FL_QLO 0
#define FL_KHI 49152
#define FL_KLO 98304
#define FL_VHI 147456
#define FL_VLO 188416
#define FL_SMEM 229376

__global__ void __launch_bounds__(256, 1) k_flash(
    const __nv_bfloat16* __restrict__ qc, const __nv_bfloat16* __restrict__ kc,
    const __nv_bfloat16* __restrict__ vc, __nv_bfloat16* __restrict__ at2) {
    extern __shared__ char sm[];
    const uint32_t sb = smem_u32(sm);
    const int tid = threadIdx.x, lane = tid & 31, wid = tid >> 5;
    const int qt = blockIdx.x, bh = blockIdx.y;
    const int b = bh >> 3, h = bh & 7;
    const char* qB = (const char*)qc + ((size_t)bh * Sq + qt * 128) * 640;
    const char* kB = (const char*)kc + ((size_t)bh * Sq) * 640;
    const char* vB = (const char*)vc + (size_t)bh * DHd * 4096;

    const int row_in = (lane & 7) + ((lane >> 3) & 1) * 8;
    const int choff = lane >> 4;
    const int lrow = tid >> 1, lhalf = tid & 1;      // for 128x20chunk loads

    // ---- prologue: stage Qhi (in VHI area) + Qlo (persistent) ----
#pragma unroll
    for (int j = 0; j < 10; j++) {
        int c = lhalf * 10 + j;
        cpa16(sb + FL_VHI + lrow * 384 + swz24(c, lrow) * 16, qB + lrow * 640 + c * 16);
        cpa16(sb + FL_QLO + lrow * 384 + swz24(c, lrow) * 16, qB + lrow * 640 + 320 + c * 16);
    }
    CP_COMMIT;
    CP_WAIT0;
    __syncthreads();

    uint32_t qhi[10][4];
    {
        int r = wid * 16 + row_in;
#pragma unroll
        for (int kf = 0; kf < 10; kf++)
            ldsm4(qhi[kf], sb + FL_VHI + r * 384 + swz24(2 * kf + choff, r) * 16);
    }
    __syncthreads();   // Qhi staging (VHI) free before V(0) load

    // ---- K/V tile loaders ----
#define LOAD_K(kt) do { \
        const char* kr = kB + ((kt) * 128 + lrow) * 640; \
        _Pragma("unroll") \
        for (int j = 0; j < 10; j++) { \
            int c = lhalf * 10 + j; \
            uint32_t so = lrow * 384 + swz24(c, lrow) * 16; \
            cpa16(sb + FL_KHI + so, kr + c * 16); \
            cpa16(sb + FL_KLO + so, kr + 320 + c * 16); \
        } \
    } while (0)
#define LOAD_V(kt) do { \
        _Pragma("unroll") \
        for (int i = 0; i < 10; i++) { \
            int idx = tid + i * 256; \
            int vr = idx >> 4, c = idx & 15; \
            uint32_t so = vr * 256 + swz16(c, vr) * 16; \
            const char* vs = vB + vr * 4096 + (kt) * 256 + c * 16; \
            cpa16(sb + FL_VHI + so, vs); \
            cpa16(sb + FL_VLO + so, vs + 2048); \
        } \
    } while (0)

    LOAD_K(0); CP_COMMIT;
    LOAD_V(0); CP_COMMIT;

    float O[20][4] = {};
    float mr0 = -1e30f, mr1 = -1e30f, lr0 = 0.f, lr1 = 0.f;
    const float cs = 0.07905694150420949f * 1.4426950408889634f;  // scale*log2e
    const int rq = wid * 16 + row_in;

    for (int kt = 0; kt < 8; kt++) {
        CP_WAIT1;            // K(kt) ready
        __syncthreads();

        // ---- S = Qhi Khi^T + Qlo Khi^T + Qhi Klo^T ----
        float accS[16][4] = {};
#pragma unroll
        for (int kf = 0; kf < 10; kf++) {
            uint32_t qlo[4];
            ldsm4(qlo, sb + FL_QLO + rq * 384 + swz24(2 * kf + choff, rq) * 16);
#pragma unroll
            for (int g = 0; g < 8; g++) {
                int r = g * 16 + row_in;
                uint32_t so = r * 384 + swz24(2 * kf + choff, r) * 16;
                uint32_t bhi[4], blo[4];
                ldsm4(bhi, sb + FL_KHI + so);
                ldsm4(blo, sb + FL_KLO + so);
                uint32_t b0[2] = { bhi[0], bhi[2] }, b1[2] = { bhi[1], bhi[3] };
                mma16816(accS[2 * g],     qhi[kf], b0);
                mma16816(accS[2 * g],     qlo,     b0);
                mma16816(accS[2 * g + 1], qhi[kf], b1);
                mma16816(accS[2 * g + 1], qlo,     b1);
                uint32_t c0[2] = { blo[0], blo[2] }, c1[2] = { blo[1], blo[3] };
                mma16816(accS[2 * g],     qhi[kf], c0);
                mma16816(accS[2 * g + 1], qhi[kf], c1);
            }
        }

        // ---- online softmax (rows lane>>2 and +8 within warp) ----
        float mx0 = -1e30f, mx1 = -1e30f;
#pragma unroll
        for (int nf = 0; nf < 16; nf++) {
            mx0 = fmaxf(mx0, fmaxf(accS[nf][0], accS[nf][1]));
            mx1 = fmaxf(mx1, fmaxf(accS[nf][2], accS[nf][3]));
        }
        mx0 = fmaxf(mx0, __shfl_xor_sync(0xffffffffu, mx0, 1));
        mx0 = fmaxf(mx0, __shfl_xor_sync(0xffffffffu, mx0, 2));
        mx1 = fmaxf(mx1, __shfl_xor_sync(0xffffffffu, mx1, 1));
        mx1 = fmaxf(mx1, __shfl_xor_sync(0xffffffffu, mx1, 2));
        float mn0 = fmaxf(mr0, mx0), mn1 = fmaxf(mr1, mx1);
        float a0 = exp2f((mr0 - mn0) * cs), a1 = exp2f((mr1 - mn1) * cs);
        float s0 = 0.f, s1 = 0.f;
#pragma unroll
        for (int nf = 0; nf < 16; nf++) {
            accS[nf][0] = exp2f((accS[nf][0] - mn0) * cs);
            accS[nf][1] = exp2f((accS[nf][1] - mn0) * cs);
            accS[nf][2] = exp2f((accS[nf][2] - mn1) * cs);
            accS[nf][3] = exp2f((accS[nf][3] - mn1) * cs);
            s0 += accS[nf][0] + accS[nf][1];
            s1 += accS[nf][2] + accS[nf][3];
        }
        s0 += __shfl_xor_sync(0xffffffffu, s0, 1);
        s0 += __shfl_xor_sync(0xffffffffu, s0, 2);
        s1 += __shfl_xor_sync(0xffffffffu, s1, 1);
        s1 += __shfl_xor_sync(0xffffffffu, s1, 2);
        lr0 = lr0 * a0 + s0;
        lr1 = lr1 * a1 + s1;
        mr0 = mn0; mr1 = mn1;
#pragma unroll
        for (int nf = 0; nf < 20; nf++) {
            O[nf][0] *= a0; O[nf][1] *= a0; O[nf][2] *= a1; O[nf][3] *= a1;
        }

        __syncthreads();                   // all warps done reading K area
        if (kt < 7) { LOAD_K(kt + 1); }
        CP_COMMIT;
        CP_WAIT1;                          // V(kt) ready (K(kt+1) pending ok)
        __syncthreads();

        // ---- O += Phi Vhi^T + Plo Vhi^T + Phi Vlo^T ----
#pragma unroll
        for (int kf = 0; kf < 8; kf++) {
            uint32_t phi[4], plo[4];
            pack_split2(accS[2 * kf][0],     accS[2 * kf][1],     phi[0], plo[0]);
            pack_split2(accS[2 * kf][2],     accS[2 * kf][3],     phi[1], plo[1]);
            pack_split2(accS[2 * kf + 1][0], accS[2 * kf + 1][1], phi[2], plo[2]);
            pack_split2(accS[2 * kf + 1][2], accS[2 * kf + 1][3], phi[3], plo[3]);
#pragma unroll
            for (int g = 0; g < 10; g++) {
                int r = g * 16 + row_in;
                uint32_t so = r * 256 + swz16(2 * kf + choff, r) * 16;
                uint32_t bhi[4], blo[4];
                ldsm4(bhi, sb + FL_VHI + so);
                ldsm4(blo, sb + FL_VLO + so);
                uint32_t b0[2] = { bhi[0], bhi[2] }, b1[2] = { bhi[1], bhi[3] };
                mma16816(O[2 * g],     phi, b0);
                mma16816(O[2 * g],     plo, b0);
                mma16816(O[2 * g + 1], phi, b1);
                mma16816(O[2 * g + 1], plo, b1);
                uint32_t c0[2] = { blo[0], blo[2] }, c1[2] = { blo[1], blo[3] };
                mma16816(O[2 * g],     phi, c0);
                mma16816(O[2 * g + 1], phi, c1);
            }
        }

        __syncthreads();                   // all warps done reading V area
        if (kt < 7) { LOAD_V(kt + 1); }
        CP_COMMIT;
    }

    // ---- epilogue: O/l -> split at2 (A-side [hi|lo|hi] for out-proj) ----
    float i0 = 1.0f / lr0, i1 = 1.0f / lr1;
    int r0 = qt * 128 + wid * 16 + (lane >> 2);
#pragma unroll
    for (int nf = 0; nf < 20; nf++) {
        int d = nf * 8 + (lane & 3) * 2;
        size_t base0 = ((size_t)(b * Sq + r0) * KP) + h * DHd + d;
        size_t base1 = ((size_t)(b * Sq + r0 + 8) * KP) + h * DHd + d;
        wr_split(at2, base0, Cc, O[nf][0] * i0, O[nf][1] * i0);
        wr_split(at2, base1, Cc, O[nf][2] * i1, O[nf][3] * i1);
    }
#undef LOAD_K
#undef LOAD_V
}

// ====================== launch ======================
#define GEMM_SMEM (3 * 32768)

extern "C" void kernel_launch(void* const* d_in, const int* in_sizes, int n_in,
                              void* d_out, int out_size) {
    const float* h  = (const float*)d_in[0];
    const float* p  = (const float*)d_in[1];
    const float* Wm = (const float*)d_in[2];
    const float* bm = (const float*)d_in[3];
    const float* wq = (const float*)d_in[4];
    const float* wk = (const float*)d_in[5];
    const float* wv = (const float*)d_in[6];
    const float* wo = (const float*)d_in[7];
    const float* bo = (const float*)d_in[8];
    const float* qd = (const float*)d_in[9];
    const float* qu = (const float*)d_in[10];
    const float* kd = (const float*)d_in[11];
    const float* ku = (const float*)d_in[12];
    const float* vd = (const float*)d_in[13];
    const float* vu = (const float*)d_in[14];
    const float* od = (const float*)d_in[15];
    const float* ou = (const float*)d_in[16];

    __nv_bfloat16 *hp2, *x2, *at2, *wm2, *we2, *wo2, *qc, *kc, *vc;
    float *qkv;
    cudaGetSymbolAddress((void**)&hp2, g_hp2);
    cudaGetSymbolAddress((void**)&x2, g_x2);
    cudaGetSymbolAddress((void**)&at2, g_at2);
    cudaGetSymbolAddress((void**)&wm2, g_wm2);
    cudaGetSymbolAddress((void**)&we2, g_we2);
    cudaGetSymbolAddress((void**)&wo2, g_wo2);
    cudaGetSymbolAddress((void**)&qkv, g_qkv);
    cudaGetSymbolAddress((void**)&qc, g_qc);
    cudaGetSymbolAddress((void**)&kc, g_kc);
    cudaGetSymbolAddress((void**)&vc, g_vc);

    cudaFuncSetAttribute(k_mma<0>, cudaFuncAttributeMaxDynamicSharedMemorySize, GEMM_SMEM);
    cudaFuncSetAttribute(k_mma<1>, cudaFuncAttributeMaxDynamicSharedMemorySize, GEMM_SMEM);
    cudaFuncSetAttribute(k_mma<2>, cudaFuncAttributeMaxDynamicSharedMemorySize, GEMM_SMEM);
    cudaFuncSetAttribute(k_flash, cudaFuncAttributeMaxDynamicSharedMemorySize, FL_SMEM);

    // 1) hp' = split(h + pose)
    k_add_split<<<(Mrows * Cc / 2 + 255) / 256, 256>>>(h, p, hp2);

    // 2) weight prep
    dim3 gw(Cc / 32, Cc / 32);
    k_wT<<<gw, 256>>>(Wm, nullptr, nullptr, wm2, 0);
    k_wT<<<gw, 256>>>(wq, qd, qu, we2, 0);
    k_wT<<<gw, 256>>>(wk, kd, ku, we2, Cc);
    k_wT<<<gw, 256>>>(wv, vd, vu, we2, 2 * Cc);
    k_wT<<<gw, 256>>>(wo, od, ou, wo2, 0);

    // 3) x = hp @ Wm + bm + h  -> split x'
    k_mma<1><<<dim3(Cc / 128, Mrows / 128), 256, GEMM_SMEM>>>(
        hp2, wm2, nullptr, x2, bm, h, KP, KP, KP / 64, Cc);

    // 4) qkv = x @ [Wq|Wk|Wv] (fp32)
    k_mma<0><<<dim3(QKV_N / 128, Mrows / 128), 256, GEMM_SMEM>>>(
        x2, we2, qkv, nullptr, nullptr, nullptr, KP, KP, KP / 64, QKV_N);

    // 5) attention prep (compact hi|lo)
    {
        size_t tot = 2ull * BH * Sq * DHd;
        k_qc<<<(unsigned)((tot + 255) / 256), 256>>>(qkv, qc, kc);
        k_vc<<<dim3(DHd / 32, Sq / 32, BH), 256>>>(qkv, vc);
    }

    // 6) fused flash attention -> split at2
    k_flash<<<dim3(Sq / 128, BH), 256, FL_SMEM>>>(qc, kc, vc, at2);

    // 7) out = attn @ Wo + bo (fp32 to d_out)
    k_mma<2><<<dim3(Cc / 128, Mrows / 128), 256, GEMM_SMEM>>>(
        at2, wo2, (float*)d_out, nullptr, bo, nullptr, KP, KP, KP / 64, Cc);
}